// round 9
// baseline (speedup 1.0000x reference)
#include <cuda_runtime.h>
#include <cuda_fp16.h>
#include <cstdint>

#define NN 50000
#define EE 800000
#define F  128
#define KT 32
#define CAP 96

// Scratch (static __device__ — no allocation anywhere)
__device__ int      g_cnt[NN];
__device__ int      g_csr[(size_t)NN * CAP];
__device__ unsigned g_pack[(size_t)NN * KT];     // (half bits << 16) | idx
__device__ __half   g_aggh[(size_t)NN * F];      // fp16 agg (exact in tf32)
__device__ float4   g_bsplit[32 * 128 * 4];      // [kb][n][slot], pre-swizzled

// ---------------------------------------------------------------------------
__device__ __forceinline__ float2 split_tf32(float x) {
    unsigned hb;
    asm("cvt.rna.tf32.f32 %0, %1;" : "=r"(hb) : "f"(x));
    float hf = __uint_as_float(hb);
    float r = x - hf;
    unsigned lb;
    asm("cvt.rna.tf32.f32 %0, %1;" : "=r"(lb) : "f"(r));
    return make_float2(hf, __uint_as_float(lb));
}

__device__ __forceinline__ void mma_tf32(float* d,
                                         float a0, float a1, float a2, float a3,
                                         float b0, float b1) {
    asm volatile(
        "mma.sync.aligned.m16n8k8.row.col.f32.tf32.tf32.f32 "
        "{%0,%1,%2,%3}, {%4,%5,%6,%7}, {%8,%9}, {%0,%1,%2,%3};"
        : "+f"(d[0]), "+f"(d[1]), "+f"(d[2]), "+f"(d[3])
        : "r"(__float_as_uint(a0)), "r"(__float_as_uint(a1)),
          "r"(__float_as_uint(a2)), "r"(__float_as_uint(a3)),
          "r"(__float_as_uint(b0)), "r"(__float_as_uint(b1)));
}

// ---------------------------------------------------------------------------
// K1: dedupe top-k (last-wins), pack (half val, idx), zero CSR counters.
// ---------------------------------------------------------------------------
__global__ void k_prep(const float* __restrict__ topk_values,
                       const int*  __restrict__ topk_indices) {
    int w = (blockIdx.x * blockDim.x + threadIdx.x) >> 5;
    int lane = threadIdx.x & 31;
    if (w >= NN) return;
    float v  = topk_values[(size_t)w * KT + lane];
    int  idx = topk_indices[(size_t)w * KT + lane];
    unsigned m = __match_any_sync(0xffffffffu, idx);
    int leader = 31 - __clz(m);
    unsigned hb = (lane == leader)
        ? (unsigned)__half_as_ushort(__float2half(v)) : 0u;
    g_pack[(size_t)w * KT + lane] = (hb << 16) | (unsigned)(idx & 0xFFFF);
    if (lane == 0) g_cnt[w] = 0;
}

// ---------------------------------------------------------------------------
// K1b: split B once into fragment-native, swizzled layout.
// slot c of row n holds (hi(k=c), lo(c), hi(c+4), lo(c+4)) at c ^ ((n>>1)&3).
// ---------------------------------------------------------------------------
__global__ void k_prepb(const float* __restrict__ Wself,
                        const float* __restrict__ Wneigh) {
    int kb = blockIdx.x;        // 0..31
    int n  = threadIdx.x;       // 0..127
    const float* B = (kb < 16) ? Wself : Wneigh;
    int kl = (kb & 15) * 8;
    float v[8];
#pragma unroll
    for (int j = 0; j < 8; j++) v[j] = B[(size_t)(kl + j) * F + n];
    int sw = (n >> 1) & 3;
#pragma unroll
    for (int c = 0; c < 4; c++) {
        float2 h0 = split_tf32(v[c]);
        float2 h1 = split_tf32(v[c + 4]);
        g_bsplit[(kb * 128 + n) * 4 + (c ^ sw)] =
            make_float4(h0.x, h0.y, h1.x, h1.y);
    }
}

// ---------------------------------------------------------------------------
// K2: fill padded CSR
// ---------------------------------------------------------------------------
__global__ void k_fill(const int* __restrict__ src,
                       const int* __restrict__ dst) {
    int e = blockIdx.x * blockDim.x + threadIdx.x;
    if (e >= EE) return;
    int d = dst[e];
    int slot = atomicAdd(&g_cnt[d], 1);
    if (slot < CAP) g_csr[(size_t)d * CAP + slot] = src[e];
}

// ---------------------------------------------------------------------------
// K3: gather SpMM — warp per dst node, smem accumulator, 4B packed entries.
// ---------------------------------------------------------------------------
__global__ __launch_bounds__(256) void k_gather() {
    __shared__ float sacc[8][F];
    int wib  = threadIdx.x >> 5;
    int lane = threadIdx.x & 31;
    int n = blockIdx.x * 8 + wib;
    if (n >= NN) return;

    float* acc = sacc[wib];
#pragma unroll
    for (int q = 0; q < 4; q++) acc[q * 32 + lane] = 0.0f;
    __syncwarp();

    int cnt = g_cnt[n];
    int deg = cnt < CAP ? cnt : CAP;

    for (int base = 0; base < deg; base += 32) {
        int eid = base + lane;
        int sl = (eid < deg) ? g_csr[(size_t)n * CAP + eid] : 0;
        int lim = deg - base; if (lim > 32) lim = 32;
        if (lim <= 0) break;
        int s0 = __shfl_sync(0xffffffffu, sl, 0);
        unsigned p = g_pack[(size_t)s0 * KT + lane];
        for (int j = 0; j < lim; j++) {
            unsigned cur = p;
            if (j + 1 < lim) {
                int s2 = __shfl_sync(0xffffffffu, sl, j + 1);
                p = g_pack[(size_t)s2 * KT + lane];
            }
            unsigned hb = cur >> 16;
            if (hb) {
                float v = __half2float(__ushort_as_half((unsigned short)hb));
                acc[cur & 127u] += v;
            }
        }
    }
    __syncwarp();

    float winv = 1.0f / (float)(cnt > 0 ? cnt : 1);
    int c0 = lane * 4;
    __half2 h01 = __floats2half2_rn(acc[c0] * winv,     acc[c0 + 1] * winv);
    __half2 h23 = __floats2half2_rn(acc[c0 + 2] * winv, acc[c0 + 3] * winv);
    uint2 st;
    st.x = *reinterpret_cast<unsigned*>(&h01);
    st.y = *reinterpret_cast<unsigned*>(&h23);
    *reinterpret_cast<uint2*>(g_aggh + (size_t)n * F + c0) = st;
}

// ---------------------------------------------------------------------------
// K4: out = [feat|agg] @ [Wself;Wneigh] + b via 3xTF32 mma (2x for fp16 agg).
// BM=64, BN=128, BK=8, grid 782, 3 CTAs/SM, double buffer, 1 barrier/tile.
// ---------------------------------------------------------------------------
__global__ __launch_bounds__(256, 3) void k_gemm(const float* __restrict__ feat,
                                                 const float* __restrict__ bias,
                                                 float* __restrict__ out) {
    __shared__ float4 As[2][64][4];    // 4 KB per buf
    __shared__ float4 Bs[2][128][4];   // 8 KB per buf

    const int m0   = blockIdx.x * 64;
    const int t    = threadIdx.x;
    const int lane = t & 31;
    const int wid  = t >> 5;
    const int wm   = wid & 1;         // 0..1 -> m offset wm*32
    const int wn   = wid >> 1;        // 0..3 -> n offset wn*32
    const int lk   = lane & 3;
    const int lq   = lane >> 2;

    // A loader role (threads 0..127): row am, k-half ah
    const int am  = t >> 1;           // 0..127 (only <64 used)
    const int ah  = t & 1;
    const int asw = (am >> 1) & 3;
    int gr = m0 + (am & 63); if (gr > NN - 1) gr = NN - 1;

    // B copy role (all 256 threads)
    const int bn0 = t >> 2;
    const int bc0 = t & 3;

    float acc[2][4][4];
#pragma unroll
    for (int mt = 0; mt < 2; mt++)
#pragma unroll
        for (int nt = 0; nt < 4; nt++)
#pragma unroll
            for (int r = 0; r < 4; r++) acc[mt][nt][r] = 0.0f;

    // Prologue: stage k-tile 0
    float4 aq = *reinterpret_cast<const float4*>(feat + (size_t)gr * F + ah * 4);
    float4 bq0 = g_bsplit[(0 * 128 + bn0) * 4 + bc0];
    float4 bq1 = g_bsplit[(0 * 128 + bn0 + 64) * 4 + bc0];

#pragma unroll 1
    for (int kb = 0; kb < 32; kb++) {
        const int buf = kb & 1;

        // ---- store staged regs -> smem (split A here) ----
        if (t < 128) {
            float2 p0 = split_tf32(aq.x), p1 = split_tf32(aq.y),
                   p2 = split_tf32(aq.z), p3 = split_tf32(aq.w);
            float2* arow = reinterpret_cast<float2*>(&As[buf][am][0]);
            arow[(0 ^ asw) * 2 + ah] = p0;
            arow[(1 ^ asw) * 2 + ah] = p1;
            arow[(2 ^ asw) * 2 + ah] = p2;
            arow[(3 ^ asw) * 2 + ah] = p3;
        }
        Bs[buf][bn0][bc0]      = bq0;
        Bs[buf][bn0 + 64][bc0] = bq1;
        __syncthreads();

        // ---- prefetch next k-tile ----
        if (kb < 31) {
            const int kn = kb + 1;
            if (t < 128) {
                if (kn < 16) {
                    aq = *reinterpret_cast<const float4*>(
                        feat + (size_t)gr * F + kn * 8 + ah * 4);
                } else {
                    uint2 u = *reinterpret_cast<const uint2*>(
                        g_aggh + (size_t)gr * F + (kn - 16) * 8 + ah * 4);
                    float2 f0 = __half22float2(*reinterpret_cast<__half2*>(&u.x));
                    float2 f1 = __half22float2(*reinterpret_cast<__half2*>(&u.y));
                    aq = make_float4(f0.x, f0.y, f1.x, f1.y);
                }
            }
            bq0 = g_bsplit[(kn * 128 + bn0) * 4 + bc0];
            bq1 = g_bsplit[(kn * 128 + bn0 + 64) * 4 + bc0];
        }

        // ---- compute current buffer ----
        float4 Afr[2][2];
#pragma unroll
        for (int mt = 0; mt < 2; mt++) {
            int r0 = wm * 32 + mt * 16 + lq;
            Afr[mt][0] = As[buf][r0][lk ^ ((r0 >> 1) & 3)];
            int r1 = r0 + 8;
            Afr[mt][1] = As[buf][r1][lk ^ ((r1 >> 1) & 3)];
        }
        float4 Bfr[4];
#pragma unroll
        for (int nt = 0; nt < 4; nt++) {
            int n = wn * 32 + nt * 8 + lq;
            Bfr[nt] = Bs[buf][n][lk ^ ((n >> 1) & 3)];
        }
        const bool full = (kb < 16);   // agg half has exact-zero A_lo
#pragma unroll
        for (int mt = 0; mt < 2; mt++) {
#pragma unroll
            for (int nt = 0; nt < 4; nt++) {
                float* d = acc[mt][nt];
                // hi * hi
                mma_tf32(d, Afr[mt][0].x, Afr[mt][1].x, Afr[mt][0].z, Afr[mt][1].z,
                            Bfr[nt].x, Bfr[nt].z);
                // hi * lo
                mma_tf32(d, Afr[mt][0].x, Afr[mt][1].x, Afr[mt][0].z, Afr[mt][1].z,
                            Bfr[nt].y, Bfr[nt].w);
                // lo * hi (skip when A_lo == 0, i.e., fp16 agg tiles)
                if (full)
                    mma_tf32(d, Afr[mt][0].y, Afr[mt][1].y, Afr[mt][0].w, Afr[mt][1].w,
                                Bfr[nt].x, Bfr[nt].z);
            }
        }
        // single barrier per tile: barrier(kb) orders compute(kb-1,buf') before
        // store(kb+1,buf') across warps.
    }

    // ---- epilogue: + bias, guarded float2 stores ----
#pragma unroll
    for (int mt = 0; mt < 2; mt++) {
        int row0 = m0 + wm * 32 + mt * 16 + lq;
#pragma unroll
        for (int nt = 0; nt < 4; nt++) {
            int col = wn * 32 + nt * 8 + 2 * lk;
            float b0 = bias[col];
            float b1 = bias[col + 1];
            float* d = acc[mt][nt];
            if (row0 < NN)
                *reinterpret_cast<float2*>(out + (size_t)row0 * F + col) =
                    make_float2(d[0] + b0, d[1] + b1);
            if (row0 + 8 < NN)
                *reinterpret_cast<float2*>(out + (size_t)(row0 + 8) * F + col) =
                    make_float2(d[2] + b0, d[3] + b1);
        }
    }
}

// ---------------------------------------------------------------------------
// Launch
// ---------------------------------------------------------------------------
extern "C" void kernel_launch(void* const* d_in, const int* in_sizes, int n_in,
                              void* d_out, int out_size) {
    const float* feat = nullptr;
    const float* tv   = nullptr;
    const int*   ti   = nullptr;
    const int*   src  = nullptr;
    const int*   dst  = nullptr;
    const float* Ws   = nullptr;
    const float* Wn   = nullptr;
    const float* bs   = nullptr;

    for (int i = 0; i < n_in; i++) {
        int sz = in_sizes[i];
        if (sz == NN * F) {
            feat = (const float*)d_in[i];
        } else if (sz == NN * KT) {
            if (!tv) tv = (const float*)d_in[i];
            else     ti = (const int*)d_in[i];
        } else if (sz == EE) {
            if (!src) src = (const int*)d_in[i];
            else      dst = (const int*)d_in[i];
        } else if (sz == F * F) {
            if (!Ws) Ws = (const float*)d_in[i];
            else     Wn = (const float*)d_in[i];
        } else if (sz == F) {
            bs = (const float*)d_in[i];
        }
    }
    float* out = (float*)d_out;

    k_prep<<<(NN + 7) / 8, 256>>>(tv, ti);
    k_prepb<<<32, 128>>>(Ws, Wn);
    k_fill<<<(EE + 255) / 256, 256>>>(src, dst);
    k_gather<<<(NN + 7) / 8, 256>>>();
    k_gemm<<<(NN + 63) / 64, 256>>>(feat, bs, out);
}

// round 11
// speedup vs baseline: 1.1604x; 1.1604x over previous
#include <cuda_runtime.h>
#include <cuda_fp16.h>
#include <cstdint>

#define NN 50000
#define EE 800000
#define F  128
#define KT 32
#define CAP 96

// Scratch (static __device__ — no allocation anywhere)
__device__ int      g_cnt[NN];
__device__ int      g_csr[(size_t)NN * CAP];
__device__ unsigned g_pack[(size_t)NN * KT];     // (half bits << 16) | idx
__device__ __half   g_aggh[(size_t)NN * F];      // fp16 agg (exact in tf32)
__device__ float4   g_bsplit[32 * 128 * 4];      // [kb][n][slot], pre-swizzled

// ---------------------------------------------------------------------------
__device__ __forceinline__ float2 split_tf32(float x) {
    unsigned hb;
    asm("cvt.rna.tf32.f32 %0, %1;" : "=r"(hb) : "f"(x));
    float hf = __uint_as_float(hb);
    float r = x - hf;
    unsigned lb;
    asm("cvt.rna.tf32.f32 %0, %1;" : "=r"(lb) : "f"(r));
    return make_float2(hf, __uint_as_float(lb));
}

__device__ __forceinline__ void mma_tf32(float* d,
                                         float a0, float a1, float a2, float a3,
                                         float b0, float b1) {
    asm volatile(
        "mma.sync.aligned.m16n8k8.row.col.f32.tf32.tf32.f32 "
        "{%0,%1,%2,%3}, {%4,%5,%6,%7}, {%8,%9}, {%0,%1,%2,%3};"
        : "+f"(d[0]), "+f"(d[1]), "+f"(d[2]), "+f"(d[3])
        : "r"(__float_as_uint(a0)), "r"(__float_as_uint(a1)),
          "r"(__float_as_uint(a2)), "r"(__float_as_uint(a3)),
          "r"(__float_as_uint(b0)), "r"(__float_as_uint(b1)));
}

// ---------------------------------------------------------------------------
// K1: dedupe top-k (last-wins), pack (half val, idx), zero CSR counters.
// ---------------------------------------------------------------------------
__global__ void k_prep(const float* __restrict__ topk_values,
                       const int*  __restrict__ topk_indices) {
    int w = (blockIdx.x * blockDim.x + threadIdx.x) >> 5;
    int lane = threadIdx.x & 31;
    if (w >= NN) return;
    float v  = topk_values[(size_t)w * KT + lane];
    int  idx = topk_indices[(size_t)w * KT + lane];
    unsigned m = __match_any_sync(0xffffffffu, idx);
    int leader = 31 - __clz(m);
    unsigned hb = (lane == leader)
        ? (unsigned)__half_as_ushort(__float2half(v)) : 0u;
    g_pack[(size_t)w * KT + lane] = (hb << 16) | (unsigned)(idx & 0xFFFF);
    if (lane == 0) g_cnt[w] = 0;
}

// ---------------------------------------------------------------------------
// K1b: split B once into fragment-native, swizzled layout.
// slot c of row n holds (hi(k=c), lo(c), hi(c+4), lo(c+4)) at c ^ ((n>>1)&3).
// ---------------------------------------------------------------------------
__global__ void k_prepb(const float* __restrict__ Wself,
                        const float* __restrict__ Wneigh) {
    int kb = blockIdx.x;        // 0..31
    int n  = threadIdx.x;       // 0..127
    const float* B = (kb < 16) ? Wself : Wneigh;
    int kl = (kb & 15) * 8;
    float v[8];
#pragma unroll
    for (int j = 0; j < 8; j++) v[j] = B[(size_t)(kl + j) * F + n];
    int sw = (n >> 1) & 3;
#pragma unroll
    for (int c = 0; c < 4; c++) {
        float2 h0 = split_tf32(v[c]);
        float2 h1 = split_tf32(v[c + 4]);
        g_bsplit[(kb * 128 + n) * 4 + (c ^ sw)] =
            make_float4(h0.x, h0.y, h1.x, h1.y);
    }
}

// ---------------------------------------------------------------------------
// K2: fill padded CSR
// ---------------------------------------------------------------------------
__global__ void k_fill(const int* __restrict__ src,
                       const int* __restrict__ dst) {
    int e = blockIdx.x * blockDim.x + threadIdx.x;
    if (e >= EE) return;
    int d = dst[e];
    int slot = atomicAdd(&g_cnt[d], 1);
    if (slot < CAP) g_csr[(size_t)d * CAP + slot] = src[e];
}

// ---------------------------------------------------------------------------
// K3: gather SpMM — warp per dst node, smem ATOMIC accumulation.
// RED.SHARED replaces the LDS->FADD->STS chain: one issued op per edge-lane,
// conflicts resolved in the atomic ALU, no cross-iteration alias ordering.
// ---------------------------------------------------------------------------
__global__ __launch_bounds__(256) void k_gather() {
    __shared__ float sacc[8][F];
    int wib  = threadIdx.x >> 5;
    int lane = threadIdx.x & 31;
    int n = blockIdx.x * 8 + wib;
    if (n >= NN) return;

    float* acc = sacc[wib];
#pragma unroll
    for (int q = 0; q < 4; q++) acc[q * 32 + lane] = 0.0f;
    __syncwarp();

    int cnt = g_cnt[n];
    int deg = cnt < CAP ? cnt : CAP;

    for (int base = 0; base < deg; base += 32) {
        int eid = base + lane;
        int sl = (eid < deg) ? __ldg(&g_csr[(size_t)n * CAP + eid]) : 0;
        int lim = deg - base; if (lim > 32) lim = 32;
        if (lim <= 0) break;
        int s0 = __shfl_sync(0xffffffffu, sl, 0);
        unsigned p = g_pack[(size_t)s0 * KT + lane];
        for (int j = 0; j < lim; j++) {
            unsigned cur = p;
            if (j + 1 < lim) {
                int s2 = __shfl_sync(0xffffffffu, sl, j + 1);
                p = g_pack[(size_t)s2 * KT + lane];
            }
            unsigned hb = cur >> 16;
            if (hb) {
                float v = __half2float(__ushort_as_half((unsigned short)hb));
                atomicAdd(&acc[cur & 127u], v);
            }
        }
    }
    __syncwarp();

    float winv = 1.0f / (float)(cnt > 0 ? cnt : 1);
    int c0 = lane * 4;
    __half2 h01 = __floats2half2_rn(acc[c0] * winv,     acc[c0 + 1] * winv);
    __half2 h23 = __floats2half2_rn(acc[c0 + 2] * winv, acc[c0 + 3] * winv);
    uint2 st;
    st.x = *reinterpret_cast<unsigned*>(&h01);
    st.y = *reinterpret_cast<unsigned*>(&h23);
    *reinterpret_cast<uint2*>(g_aggh + (size_t)n * F + c0) = st;
}

// ---------------------------------------------------------------------------
// K4: out = [feat|agg] @ [Wself;Wneigh] + b via 3xTF32 mma (2x for fp16 agg).
// BM=64, BN=128, BK=8, grid 782, regs UNCAPPED (no spills), double buffer.
// ---------------------------------------------------------------------------
__global__ __launch_bounds__(256) void k_gemm(const float* __restrict__ feat,
                                              const float* __restrict__ bias,
                                              float* __restrict__ out) {
    __shared__ float4 As[2][64][4];    // 4 KB per buf
    __shared__ float4 Bs[2][128][4];   // 8 KB per buf

    const int m0   = blockIdx.x * 64;
    const int t    = threadIdx.x;
    const int lane = t & 31;
    const int wid  = t >> 5;
    const int wm   = wid & 1;         // 0..1 -> m offset wm*32
    const int wn   = wid >> 1;        // 0..3 -> n offset wn*32
    const int lk   = lane & 3;
    const int lq   = lane >> 2;

    // A loader role (threads 0..127): row am, k-half ah
    const int am  = t >> 1;           // 0..127 (only <64 used)
    const int ah  = t & 1;
    const int asw = (am >> 1) & 3;
    int gr = m0 + (am & 63); if (gr > NN - 1) gr = NN - 1;

    // B copy role (all 256 threads)
    const int bn0 = t >> 2;
    const int bc0 = t & 3;

    float acc[2][4][4];
#pragma unroll
    for (int mt = 0; mt < 2; mt++)
#pragma unroll
        for (int nt = 0; nt < 4; nt++)
#pragma unroll
            for (int r = 0; r < 4; r++) acc[mt][nt][r] = 0.0f;

    // Prologue: stage k-tile 0
    float4 aq = *reinterpret_cast<const float4*>(feat + (size_t)gr * F + ah * 4);
    float4 bq0 = g_bsplit[(0 * 128 + bn0) * 4 + bc0];
    float4 bq1 = g_bsplit[(0 * 128 + bn0 + 64) * 4 + bc0];

#pragma unroll 1
    for (int kb = 0; kb < 32; kb++) {
        const int buf = kb & 1;

        // ---- store staged regs -> smem (split A here) ----
        if (t < 128) {
            float2 p0 = split_tf32(aq.x), p1 = split_tf32(aq.y),
                   p2 = split_tf32(aq.z), p3 = split_tf32(aq.w);
            float2* arow = reinterpret_cast<float2*>(&As[buf][am][0]);
            arow[(0 ^ asw) * 2 + ah] = p0;
            arow[(1 ^ asw) * 2 + ah] = p1;
            arow[(2 ^ asw) * 2 + ah] = p2;
            arow[(3 ^ asw) * 2 + ah] = p3;
        }
        Bs[buf][bn0][bc0]      = bq0;
        Bs[buf][bn0 + 64][bc0] = bq1;
        __syncthreads();

        // ---- prefetch next k-tile ----
        if (kb < 31) {
            const int kn = kb + 1;
            if (t < 128) {
                if (kn < 16) {
                    aq = *reinterpret_cast<const float4*>(
                        feat + (size_t)gr * F + kn * 8 + ah * 4);
                } else {
                    uint2 u = *reinterpret_cast<const uint2*>(
                        g_aggh + (size_t)gr * F + (kn - 16) * 8 + ah * 4);
                    float2 f0 = __half22float2(*reinterpret_cast<__half2*>(&u.x));
                    float2 f1 = __half22float2(*reinterpret_cast<__half2*>(&u.y));
                    aq = make_float4(f0.x, f0.y, f1.x, f1.y);
                }
            }
            bq0 = g_bsplit[(kn * 128 + bn0) * 4 + bc0];
            bq1 = g_bsplit[(kn * 128 + bn0 + 64) * 4 + bc0];
        }

        // ---- compute current buffer ----
        float4 Afr[2][2];
#pragma unroll
        for (int mt = 0; mt < 2; mt++) {
            int r0 = wm * 32 + mt * 16 + lq;
            Afr[mt][0] = As[buf][r0][lk ^ ((r0 >> 1) & 3)];
            int r1 = r0 + 8;
            Afr[mt][1] = As[buf][r1][lk ^ ((r1 >> 1) & 3)];
        }
        float4 Bfr[4];
#pragma unroll
        for (int nt = 0; nt < 4; nt++) {
            int n = wn * 32 + nt * 8 + lq;
            Bfr[nt] = Bs[buf][n][lk ^ ((n >> 1) & 3)];
        }
        const bool full = (kb < 16);   // agg half has exact-zero A_lo
#pragma unroll
        for (int mt = 0; mt < 2; mt++) {
#pragma unroll
            for (int nt = 0; nt < 4; nt++) {
                float* d = acc[mt][nt];
                // hi * hi
                mma_tf32(d, Afr[mt][0].x, Afr[mt][1].x, Afr[mt][0].z, Afr[mt][1].z,
                            Bfr[nt].x, Bfr[nt].z);
                // hi * lo
                mma_tf32(d, Afr[mt][0].x, Afr[mt][1].x, Afr[mt][0].z, Afr[mt][1].z,
                            Bfr[nt].y, Bfr[nt].w);
                // lo * hi (skip when A_lo == 0, i.e., fp16 agg tiles)
                if (full)
                    mma_tf32(d, Afr[mt][0].y, Afr[mt][1].y, Afr[mt][0].w, Afr[mt][1].w,
                                Bfr[nt].x, Bfr[nt].z);
            }
        }
    }

    // ---- epilogue: + bias, guarded float2 stores ----
#pragma unroll
    for (int mt = 0; mt < 2; mt++) {
        int row0 = m0 + wm * 32 + mt * 16 + lq;
#pragma unroll
        for (int nt = 0; nt < 4; nt++) {
            int col = wn * 32 + nt * 8 + 2 * lk;
            float b0 = bias[col];
            float b1 = bias[col + 1];
            float* d = acc[mt][nt];
            if (row0 < NN)
                *reinterpret_cast<float2*>(out + (size_t)row0 * F + col) =
                    make_float2(d[0] + b0, d[1] + b1);
            if (row0 + 8 < NN)
                *reinterpret_cast<float2*>(out + (size_t)(row0 + 8) * F + col) =
                    make_float2(d[2] + b0, d[3] + b1);
        }
    }
}

// ---------------------------------------------------------------------------
// Launch
// ---------------------------------------------------------------------------
extern "C" void kernel_launch(void* const* d_in, const int* in_sizes, int n_in,
                              void* d_out, int out_size) {
    const float* feat = nullptr;
    const float* tv   = nullptr;
    const int*   ti   = nullptr;
    const int*   src  = nullptr;
    const int*   dst  = nullptr;
    const float* Ws   = nullptr;
    const float* Wn   = nullptr;
    const float* bs   = nullptr;

    for (int i = 0; i < n_in; i++) {
        int sz = in_sizes[i];
        if (sz == NN * F) {
            feat = (const float*)d_in[i];
        } else if (sz == NN * KT) {
            if (!tv) tv = (const float*)d_in[i];
            else     ti = (const int*)d_in[i];
        } else if (sz == EE) {
            if (!src) src = (const int*)d_in[i];
            else      dst = (const int*)d_in[i];
        } else if (sz == F * F) {
            if (!Ws) Ws = (const float*)d_in[i];
            else     Wn = (const float*)d_in[i];
        } else if (sz == F) {
            bs = (const float*)d_in[i];
        }
    }
    float* out = (float*)d_out;

    k_prep<<<(NN + 7) / 8, 256>>>(tv, ti);
    k_prepb<<<32, 128>>>(Ws, Wn);
    k_fill<<<(EE + 255) / 256, 256>>>(src, dst);
    k_gather<<<(NN + 7) / 8, 256>>>();
    k_gemm<<<(NN + 63) / 64, 256>>>(feat, bs, out);
}

// round 12
// speedup vs baseline: 1.3355x; 1.1510x over previous
#include <cuda_runtime.h>
#include <cuda_fp16.h>
#include <cstdint>

#define NN 50000
#define EE 800000
#define F  128
#define KT 32
#define CAP 96

// Scratch (static __device__ — no allocation anywhere)
__device__ int    g_cnt[NN];
__device__ int    g_csr[(size_t)NN * CAP];
__device__ __half g_xsh[(size_t)NN * F];      // dense fp16 x_sparse rows
__device__ __half g_aggh[(size_t)NN * F];     // fp16 agg (exact in tf32)
__device__ float4 g_bsplit[32 * 128 * 4];     // [kb][n][slot], pre-swizzled

// ---------------------------------------------------------------------------
__device__ __forceinline__ float2 split_tf32(float x) {
    unsigned hb;
    asm("cvt.rna.tf32.f32 %0, %1;" : "=r"(hb) : "f"(x));
    float hf = __uint_as_float(hb);
    float r = x - hf;
    unsigned lb;
    asm("cvt.rna.tf32.f32 %0, %1;" : "=r"(lb) : "f"(r));
    return make_float2(hf, __uint_as_float(lb));
}

__device__ __forceinline__ void mma_tf32(float* d,
                                         float a0, float a1, float a2, float a3,
                                         float b0, float b1) {
    asm volatile(
        "mma.sync.aligned.m16n8k8.row.col.f32.tf32.tf32.f32 "
        "{%0,%1,%2,%3}, {%4,%5,%6,%7}, {%8,%9}, {%0,%1,%2,%3};"
        : "+f"(d[0]), "+f"(d[1]), "+f"(d[2]), "+f"(d[3])
        : "r"(__float_as_uint(a0)), "r"(__float_as_uint(a1)),
          "r"(__float_as_uint(a2)), "r"(__float_as_uint(a3)),
          "r"(__float_as_uint(b0)), "r"(__float_as_uint(b1)));
}

// ---------------------------------------------------------------------------
// K1: expand top-k into DENSE fp16 x_sparse rows (last-wins dedup),
//     zero CSR counters. One warp per node.
// ---------------------------------------------------------------------------
__global__ __launch_bounds__(256) void k_expand(
        const float* __restrict__ topk_values,
        const int*  __restrict__ topk_indices) {
    __shared__ __half srow[8][F];
    int wib  = threadIdx.x >> 5;
    int lane = threadIdx.x & 31;
    int w = blockIdx.x * 8 + wib;
    if (w >= NN) return;

    // zero the row (lane writes 4 halves = 8B)
    *reinterpret_cast<uint2*>(&srow[wib][lane * 4]) = make_uint2(0u, 0u);
    __syncwarp();

    float v  = topk_values[(size_t)w * KT + lane];
    int  idx = topk_indices[(size_t)w * KT + lane];
    unsigned m = __match_any_sync(0xffffffffu, idx);
    int leader = 31 - __clz(m);          // highest lane with this index wins
    if (lane == leader)
        srow[wib][idx & 127] = __float2half(v);
    __syncwarp();

    *reinterpret_cast<uint2*>(g_xsh + (size_t)w * F + lane * 4) =
        *reinterpret_cast<uint2*>(&srow[wib][lane * 4]);
    if (lane == 0) g_cnt[w] = 0;
}

// ---------------------------------------------------------------------------
// K1b: split B once into fragment-native, swizzled layout.
// slot c of row n holds (hi(k=c), lo(c), hi(c+4), lo(c+4)) at c ^ ((n>>1)&3).
// ---------------------------------------------------------------------------
__global__ void k_prepb(const float* __restrict__ Wself,
                        const float* __restrict__ Wneigh) {
    int kb = blockIdx.x;        // 0..31
    int n  = threadIdx.x;       // 0..127
    const float* B = (kb < 16) ? Wself : Wneigh;
    int kl = (kb & 15) * 8;
    float v[8];
#pragma unroll
    for (int j = 0; j < 8; j++) v[j] = B[(size_t)(kl + j) * F + n];
    int sw = (n >> 1) & 3;
#pragma unroll
    for (int c = 0; c < 4; c++) {
        float2 h0 = split_tf32(v[c]);
        float2 h1 = split_tf32(v[c + 4]);
        g_bsplit[(kb * 128 + n) * 4 + (c ^ sw)] =
            make_float4(h0.x, h0.y, h1.x, h1.y);
    }
}

// ---------------------------------------------------------------------------
// K2: fill padded CSR (in-degree lands in g_cnt)
// ---------------------------------------------------------------------------
__global__ void k_fill(const int* __restrict__ src,
                       const int* __restrict__ dst) {
    int e = blockIdx.x * blockDim.x + threadIdx.x;
    if (e >= EE) return;
    int d = dst[e];
    int slot = atomicAdd(&g_cnt[d], 1);
    if (slot < CAP) g_csr[(size_t)d * CAP + slot] = src[e];
}

// ---------------------------------------------------------------------------
// K3: gather SpMM — warp per dst, REGISTER accumulation over dense fp16 rows.
// Lane owns 4 feature columns; per edge: one coalesced LDG.64 + 4 FADD.
// No smem, no conflicts, no atomics.
// ---------------------------------------------------------------------------
__global__ __launch_bounds__(256) void k_gather() {
    int wib  = threadIdx.x >> 5;
    int lane = threadIdx.x & 31;
    int n = blockIdx.x * 8 + wib;
    if (n >= NN) return;

    float a0 = 0.f, a1 = 0.f, a2 = 0.f, a3 = 0.f;

    int cnt = g_cnt[n];
    int deg = cnt < CAP ? cnt : CAP;

    for (int base = 0; base < deg; base += 32) {
        int eid = base + lane;
        int sl = (eid < deg) ? __ldg(&g_csr[(size_t)n * CAP + eid]) : 0;
        int lim = deg - base; if (lim > 32) lim = 32;
        for (int j = 0; j < lim; j++) {
            int s = __shfl_sync(0xffffffffu, sl, j);
            uint2 u = *reinterpret_cast<const uint2*>(
                g_xsh + (size_t)s * F + lane * 4);
            float2 f0 = __half22float2(*reinterpret_cast<__half2*>(&u.x));
            float2 f1 = __half22float2(*reinterpret_cast<__half2*>(&u.y));
            a0 += f0.x; a1 += f0.y; a2 += f1.x; a3 += f1.y;
        }
    }

    float winv = 1.0f / (float)(cnt > 0 ? cnt : 1);
    __half2 h01 = __floats2half2_rn(a0 * winv, a1 * winv);
    __half2 h23 = __floats2half2_rn(a2 * winv, a3 * winv);
    uint2 st;
    st.x = *reinterpret_cast<unsigned*>(&h01);
    st.y = *reinterpret_cast<unsigned*>(&h23);
    *reinterpret_cast<uint2*>(g_aggh + (size_t)n * F + lane * 4) = st;
}

// ---------------------------------------------------------------------------
// K4: out = [feat|agg] @ [Wself;Wneigh] + b via 3xTF32 mma.
// EXACT 148.2-run config: BM=128, BN=128, BK=8, launch_bounds(256,2),
// double buffer, fragment-native swizzled smem — plus fp16-agg A reads and
// lo*hi mma skip for k-tiles 16..31 (A_lo == 0 exactly for fp16 inputs).
// ---------------------------------------------------------------------------
__global__ __launch_bounds__(256, 2) void k_gemm(const float* __restrict__ feat,
                                                 const float* __restrict__ bias,
                                                 float* __restrict__ out) {
    __shared__ float4 As[2][128][4];   // 8 KB per buf
    __shared__ float4 Bs[2][128][4];

    const int m0   = blockIdx.x * 128;
    const int t    = threadIdx.x;
    const int lane = t & 31;
    const int wid  = t >> 5;
    const int wm   = wid >> 1;        // 0..3
    const int wn   = wid & 1;         // 0..1
    const int lk   = lane & 3;
    const int lq   = lane >> 2;

    // A loader role: row am, k-quad ah
    const int am  = t >> 1;
    const int ah  = t & 1;
    const int asw = (am >> 1) & 3;
    int gr = m0 + am; if (gr > NN - 1) gr = NN - 1;

    // B copy role
    const int bn0 = t >> 2;
    const int bc0 = t & 3;

    float acc[2][8][4];
#pragma unroll
    for (int mt = 0; mt < 2; mt++)
#pragma unroll
        for (int nt = 0; nt < 8; nt++)
#pragma unroll
            for (int r = 0; r < 4; r++) acc[mt][nt][r] = 0.0f;

    // Prologue: stage k-tile 0
    float4 aq  = *reinterpret_cast<const float4*>(feat + (size_t)gr * F + ah * 4);
    float4 bq0 = g_bsplit[(0 * 128 + bn0) * 4 + bc0];
    float4 bq1 = g_bsplit[(0 * 128 + bn0 + 64) * 4 + bc0];

#pragma unroll 1
    for (int kb = 0; kb < 32; kb++) {
        const int buf = kb & 1;

        // ---- store staged regs -> smem (split A here) ----
        {
            float2 p0 = split_tf32(aq.x), p1 = split_tf32(aq.y),
                   p2 = split_tf32(aq.z), p3 = split_tf32(aq.w);
            float2* arow = reinterpret_cast<float2*>(&As[buf][am][0]);
            arow[(0 ^ asw) * 2 + ah] = p0;
            arow[(1 ^ asw) * 2 + ah] = p1;
            arow[(2 ^ asw) * 2 + ah] = p2;
            arow[(3 ^ asw) * 2 + ah] = p3;
        }
        Bs[buf][bn0][bc0]      = bq0;
        Bs[buf][bn0 + 64][bc0] = bq1;
        __syncthreads();

        // ---- prefetch next k-tile ----
        if (kb < 31) {
            const int kn = kb + 1;
            if (kn < 16) {
                aq = *reinterpret_cast<const float4*>(
                    feat + (size_t)gr * F + kn * 8 + ah * 4);
            } else {
                uint2 u = *reinterpret_cast<const uint2*>(
                    g_aggh + (size_t)gr * F + (kn - 16) * 8 + ah * 4);
                float2 f0 = __half22float2(*reinterpret_cast<__half2*>(&u.x));
                float2 f1 = __half22float2(*reinterpret_cast<__half2*>(&u.y));
                aq = make_float4(f0.x, f0.y, f1.x, f1.y);
            }
            bq0 = g_bsplit[(kn * 128 + bn0) * 4 + bc0];
            bq1 = g_bsplit[(kn * 128 + bn0 + 64) * 4 + bc0];
        }

        // ---- compute current buffer ----
        float4 Afr[2][2];
#pragma unroll
        for (int mt = 0; mt < 2; mt++) {
            int r0 = wm * 32 + mt * 16 + lq;
            Afr[mt][0] = As[buf][r0][lk ^ ((r0 >> 1) & 3)];
            int r1 = r0 + 8;
            Afr[mt][1] = As[buf][r1][lk ^ ((r1 >> 1) & 3)];
        }
        const bool full = (kb < 16);   // agg half has exact-zero A_lo
#pragma unroll
        for (int half = 0; half < 2; half++) {
            float4 Bfr[4];
#pragma unroll
            for (int q = 0; q < 4; q++) {
                int n = wn * 64 + (half * 4 + q) * 8 + lq;
                Bfr[q] = Bs[buf][n][lk ^ ((n >> 1) & 3)];
            }
#pragma unroll
            for (int mt = 0; mt < 2; mt++) {
#pragma unroll
                for (int q = 0; q < 4; q++) {
                    float* d = acc[mt][half * 4 + q];
                    // hi * hi
                    mma_tf32(d, Afr[mt][0].x, Afr[mt][1].x, Afr[mt][0].z, Afr[mt][1].z,
                                Bfr[q].x, Bfr[q].z);
                    // hi * lo
                    mma_tf32(d, Afr[mt][0].x, Afr[mt][1].x, Afr[mt][0].z, Afr[mt][1].z,
                                Bfr[q].y, Bfr[q].w);
                    // lo * hi (skip on fp16-agg tiles)
                    if (full)
                        mma_tf32(d, Afr[mt][0].y, Afr[mt][1].y, Afr[mt][0].w, Afr[mt][1].w,
                                    Bfr[q].x, Bfr[q].z);
                }
            }
        }
    }

    // ---- epilogue: + bias, guarded float2 stores ----
#pragma unroll
    for (int mt = 0; mt < 2; mt++) {
        int row0 = m0 + wm * 32 + mt * 16 + lq;
#pragma unroll
        for (int nt = 0; nt < 8; nt++) {
            int col = wn * 64 + nt * 8 + 2 * lk;
            float b0 = bias[col];
            float b1 = bias[col + 1];
            float* d = acc[mt][nt];
            if (row0 < NN)
                *reinterpret_cast<float2*>(out + (size_t)row0 * F + col) =
                    make_float2(d[0] + b0, d[1] + b1);
            if (row0 + 8 < NN)
                *reinterpret_cast<float2*>(out + (size_t)(row0 + 8) * F + col) =
                    make_float2(d[2] + b0, d[3] + b1);
        }
    }
}

// ---------------------------------------------------------------------------
// Launch
// ---------------------------------------------------------------------------
extern "C" void kernel_launch(void* const* d_in, const int* in_sizes, int n_in,
                              void* d_out, int out_size) {
    const float* feat = nullptr;
    const float* tv   = nullptr;
    const int*   ti   = nullptr;
    const int*   src  = nullptr;
    const int*   dst  = nullptr;
    const float* Ws   = nullptr;
    const float* Wn   = nullptr;
    const float* bs   = nullptr;

    for (int i = 0; i < n_in; i++) {
        int sz = in_sizes[i];
        if (sz == NN * F) {
            feat = (const float*)d_in[i];
        } else if (sz == NN * KT) {
            if (!tv) tv = (const float*)d_in[i];
            else     ti = (const int*)d_in[i];
        } else if (sz == EE) {
            if (!src) src = (const int*)d_in[i];
            else      dst = (const int*)d_in[i];
        } else if (sz == F * F) {
            if (!Ws) Ws = (const float*)d_in[i];
            else     Wn = (const float*)d_in[i];
        } else if (sz == F) {
            bs = (const float*)d_in[i];
        }
    }
    float* out = (float*)d_out;

    k_expand<<<(NN + 7) / 8, 256>>>(tv, ti);
    k_prepb<<<32, 128>>>(Ws, Wn);
    k_fill<<<(EE + 255) / 256, 256>>>(src, dst);
    k_gather<<<(NN + 7) / 8, 256>>>();
    k_gemm<<<(NN + 127) / 128, 256>>>(feat, bs, out);
}

// round 13
// speedup vs baseline: 1.7671x; 1.3231x over previous
#include <cuda_runtime.h>
#include <cuda_fp16.h>
#include <cstdint>

#define NN 50000
#define EE 800000
#define F  128
#define KT 32
#define CAP 96

// Scratch (static __device__ — no allocation anywhere)
__device__ int    g_cnt[NN];
__device__ int    g_csr[(size_t)NN * CAP];
__device__ __half g_xsh[(size_t)NN * F];      // dense fp16 x_sparse rows
__device__ __half g_aggh[(size_t)NN * F];     // fp16 agg
__device__ uint4  g_bs16[16 * 512];           // B split fp16, fragment-native

// ---------------------------------------------------------------------------
__device__ __forceinline__ unsigned pack2(float x, float y) {
    __half2 h = __floats2half2_rn(x, y);
    return *reinterpret_cast<unsigned*>(&h);
}
__device__ __forceinline__ void split16(float x, float& h, float& l) {
    __half hh = __float2half_rn(x);
    h = __half2float(hh);
    l = x - h;
}
__device__ __forceinline__ void mma_f16(float* d,
                                        unsigned a0, unsigned a1,
                                        unsigned a2, unsigned a3,
                                        unsigned b0, unsigned b1) {
    asm volatile(
        "mma.sync.aligned.m16n8k16.row.col.f32.f16.f16.f32 "
        "{%0,%1,%2,%3}, {%4,%5,%6,%7}, {%8,%9}, {%0,%1,%2,%3};"
        : "+f"(d[0]), "+f"(d[1]), "+f"(d[2]), "+f"(d[3])
        : "r"(a0), "r"(a1), "r"(a2), "r"(a3), "r"(b0), "r"(b1));
}

// ---------------------------------------------------------------------------
// K1: expand top-k into DENSE fp16 x_sparse rows (last-wins dedup),
//     zero CSR counters. One warp per node.
// ---------------------------------------------------------------------------
__global__ __launch_bounds__(256) void k_expand(
        const float* __restrict__ topk_values,
        const int*  __restrict__ topk_indices) {
    __shared__ __half srow[8][F];
    int wib  = threadIdx.x >> 5;
    int lane = threadIdx.x & 31;
    int w = blockIdx.x * 8 + wib;
    if (w >= NN) return;

    *reinterpret_cast<uint2*>(&srow[wib][lane * 4]) = make_uint2(0u, 0u);
    __syncwarp();

    float v  = topk_values[(size_t)w * KT + lane];
    int  idx = topk_indices[(size_t)w * KT + lane];
    unsigned m = __match_any_sync(0xffffffffu, idx);
    int leader = 31 - __clz(m);          // highest lane with this index wins
    if (lane == leader)
        srow[wib][idx & 127] = __float2half(v);
    __syncwarp();

    *reinterpret_cast<uint2*>(g_xsh + (size_t)w * F + lane * 4) =
        *reinterpret_cast<uint2*>(&srow[wib][lane * 4]);
    if (lane == 0) g_cnt[w] = 0;
}

// ---------------------------------------------------------------------------
// K1b: split B (fp32 -> fp16 hi/lo) into fragment-native layout, once.
// For k16-step ks, col n, slot j: uint4 =
//   (hi2(k=2j,2j+1), hi2(2j+8,2j+9), lo2(2j,2j+1), lo2(2j+8,2j+9))
// ---------------------------------------------------------------------------
__global__ void k_prepb(const float* __restrict__ Wself,
                        const float* __restrict__ Wneigh) {
    int ks = blockIdx.x;          // 0..15
    int t  = threadIdx.x;         // 0..511
    int n  = t >> 2;
    int j  = t & 3;
    const float* W = (ks < 8) ? Wself : Wneigh;
    int kl = (ks & 7) * 16;
    float w0 = W[(size_t)(kl + 2 * j)     * F + n];
    float w1 = W[(size_t)(kl + 2 * j + 1) * F + n];
    float w2 = W[(size_t)(kl + 2 * j + 8) * F + n];
    float w3 = W[(size_t)(kl + 2 * j + 9) * F + n];
    float h0, l0, h1, l1, h2, l2, h3, l3;
    split16(w0, h0, l0); split16(w1, h1, l1);
    split16(w2, h2, l2); split16(w3, h3, l3);
    uint4 v;
    v.x = pack2(h0, h1);
    v.y = pack2(h2, h3);
    v.z = pack2(l0, l1);
    v.w = pack2(l2, l3);
    g_bs16[ks * 512 + n * 4 + j] = v;
}

// ---------------------------------------------------------------------------
// K2: fill padded CSR (in-degree lands in g_cnt)
// ---------------------------------------------------------------------------
__global__ void k_fill(const int* __restrict__ src,
                       const int* __restrict__ dst) {
    int e = blockIdx.x * blockDim.x + threadIdx.x;
    if (e >= EE) return;
    int d = dst[e];
    int slot = atomicAdd(&g_cnt[d], 1);
    if (slot < CAP) g_csr[(size_t)d * CAP + slot] = src[e];
}

// ---------------------------------------------------------------------------
// K3: gather SpMM — warp per dst, register accumulation over dense fp16 rows.
// ---------------------------------------------------------------------------
__global__ __launch_bounds__(256) void k_gather() {
    int wib  = threadIdx.x >> 5;
    int lane = threadIdx.x & 31;
    int n = blockIdx.x * 8 + wib;
    if (n >= NN) return;

    float a0 = 0.f, a1 = 0.f, a2 = 0.f, a3 = 0.f;

    int cnt = g_cnt[n];
    int deg = cnt < CAP ? cnt : CAP;

    for (int base = 0; base < deg; base += 32) {
        int eid = base + lane;
        int sl = (eid < deg) ? __ldg(&g_csr[(size_t)n * CAP + eid]) : 0;
        int lim = deg - base; if (lim > 32) lim = 32;
        for (int j = 0; j < lim; j++) {
            int s = __shfl_sync(0xffffffffu, sl, j);
            uint2 u = *reinterpret_cast<const uint2*>(
                g_xsh + (size_t)s * F + lane * 4);
            float2 f0 = __half22float2(*reinterpret_cast<__half2*>(&u.x));
            float2 f1 = __half22float2(*reinterpret_cast<__half2*>(&u.y));
            a0 += f0.x; a1 += f0.y; a2 += f1.x; a3 += f1.y;
        }
    }

    float winv = 1.0f / (float)(cnt > 0 ? cnt : 1);
    __half2 h01 = __floats2half2_rn(a0 * winv, a1 * winv);
    __half2 h23 = __floats2half2_rn(a2 * winv, a3 * winv);
    uint2 st;
    st.x = *reinterpret_cast<unsigned*>(&h01);
    st.y = *reinterpret_cast<unsigned*>(&h23);
    *reinterpret_cast<uint2*>(g_aggh + (size_t)n * F + lane * 4) = st;
}

// ---------------------------------------------------------------------------
// K4: out = [feat|agg] @ [Wself;Wneigh] + b via split-FP16 HMMA m16n8k16.
// BM=128, BN=128, BK=16, 16 k-steps, double buffer, 1 barrier/step.
// A/B smem layout: [row][slot] uint4 = (hi_lowk, hi_highk, lo_lowk, lo_highk)
// -> LDS.128/STS.128 conflict-free; one load = full hi+lo fragment pair.
// feat steps: 3 HMMA/tile (hi*bhi + hi*blo + lo*bhi); agg steps: 2 (A_lo==0).
// ---------------------------------------------------------------------------
__global__ __launch_bounds__(256, 2) void k_gemm(const float* __restrict__ feat,
                                                 const float* __restrict__ bias,
                                                 float* __restrict__ out) {
    __shared__ uint4 As[2][128][4];   // 8 KB per buf
    __shared__ uint4 Bs[2][128][4];

    const int m0   = blockIdx.x * 128;
    const int t    = threadIdx.x;
    const int lane = t & 31;
    const int wid  = t >> 5;
    const int wm   = wid >> 1;        // 0..3 -> m offset wm*32
    const int wn   = wid & 1;         // 0..1 -> n offset wn*64
    const int lk   = lane & 3;
    const int lq   = lane >> 2;

    // A loader: 4 threads per row, 2 row-passes (ar, ar+64); slot aj.
    const int ar = t >> 2;            // 0..63
    const int aj = t & 3;
    int gr0 = m0 + ar;      if (gr0 > NN - 1) gr0 = NN - 1;
    int gr1 = m0 + ar + 64; if (gr1 > NN - 1) gr1 = NN - 1;

    // B copy: uint4s t and t+256 of the 512-uint4 step block
    const int bn0 = t >> 2;
    const int bc0 = t & 3;

    float acc[2][8][4];
#pragma unroll
    for (int mt = 0; mt < 2; mt++)
#pragma unroll
        for (int nt = 0; nt < 8; nt++)
#pragma unroll
            for (int r = 0; r < 4; r++) acc[mt][nt][r] = 0.0f;

    // Staging regs
    float2 fa[2][2];   // feat: [pass][k-half] (k=2aj.., k=2aj+8..)
    uint2  ua[2];      // agg:  [pass] (halves 2aj..2aj+1, 2aj+8..2aj+9)
    uint4  bq0, bq1;

    // Prologue: stage k-step 0 (feat)
    {
        const float* p0 = feat + (size_t)gr0 * F + 2 * aj;
        const float* p1 = feat + (size_t)gr1 * F + 2 * aj;
        fa[0][0] = *reinterpret_cast<const float2*>(p0);
        fa[0][1] = *reinterpret_cast<const float2*>(p0 + 8);
        fa[1][0] = *reinterpret_cast<const float2*>(p1);
        fa[1][1] = *reinterpret_cast<const float2*>(p1 + 8);
        bq0 = g_bs16[t];
        bq1 = g_bs16[256 + t];
    }

#pragma unroll 1
    for (int kb = 0; kb < 16; kb++) {
        const int buf = kb & 1;
        const bool cur_feat = (kb < 8);

        // ---- store staged regs -> smem (split A here) ----
        if (cur_feat) {
#pragma unroll
            for (int p = 0; p < 2; p++) {
                float h0, l0, h1, l1, h2, l2, h3, l3;
                split16(fa[p][0].x, h0, l0); split16(fa[p][0].y, h1, l1);
                split16(fa[p][1].x, h2, l2); split16(fa[p][1].y, h3, l3);
                uint4 v;
                v.x = pack2(h0, h1);
                v.y = pack2(h2, h3);
                v.z = pack2(l0, l1);
                v.w = pack2(l2, l3);
                As[buf][ar + p * 64][aj] = v;
            }
        } else {
#pragma unroll
            for (int p = 0; p < 2; p++) {
                uint4 v;
                v.x = ua[p].x; v.y = ua[p].y; v.z = 0u; v.w = 0u;
                As[buf][ar + p * 64][aj] = v;
            }
        }
        Bs[buf][bn0][bc0]      = bq0;
        Bs[buf][bn0 + 64][bc0] = bq1;
        __syncthreads();

        // ---- prefetch next k-step ----
        if (kb < 15) {
            const int kn = kb + 1;
            if (kn < 8) {
                const float* p0 = feat + (size_t)gr0 * F + kn * 16 + 2 * aj;
                const float* p1 = feat + (size_t)gr1 * F + kn * 16 + 2 * aj;
                fa[0][0] = *reinterpret_cast<const float2*>(p0);
                fa[0][1] = *reinterpret_cast<const float2*>(p0 + 8);
                fa[1][0] = *reinterpret_cast<const float2*>(p1);
                fa[1][1] = *reinterpret_cast<const float2*>(p1 + 8);
            } else {
                const __half* q0 = g_aggh + (size_t)gr0 * F + (kn - 8) * 16 + 2 * aj;
                const __half* q1 = g_aggh + (size_t)gr1 * F + (kn - 8) * 16 + 2 * aj;
                ua[0].x = *reinterpret_cast<const unsigned*>(q0);
                ua[0].y = *reinterpret_cast<const unsigned*>(q0 + 8);
                ua[1].x = *reinterpret_cast<const unsigned*>(q1);
                ua[1].y = *reinterpret_cast<const unsigned*>(q1 + 8);
            }
            bq0 = g_bs16[kn * 512 + t];
            bq1 = g_bs16[kn * 512 + 256 + t];
        }

        // ---- compute current buffer ----
        uint4 qa[2][2];
#pragma unroll
        for (int mt = 0; mt < 2; mt++) {
            int r0 = wm * 32 + mt * 16 + lq;
            qa[mt][0] = As[buf][r0][lk];
            qa[mt][1] = As[buf][r0 + 8][lk];
        }
#pragma unroll
        for (int nt = 0; nt < 8; nt++) {
            uint4 qb = Bs[buf][wn * 64 + nt * 8 + lq][lk];
#pragma unroll
            for (int mt = 0; mt < 2; mt++) {
                float* d = acc[mt][nt];
                // Ahi * Bhi
                mma_f16(d, qa[mt][0].x, qa[mt][1].x, qa[mt][0].y, qa[mt][1].y,
                        qb.x, qb.y);
                // Ahi * Blo
                mma_f16(d, qa[mt][0].x, qa[mt][1].x, qa[mt][0].y, qa[mt][1].y,
                        qb.z, qb.w);
                // Alo * Bhi (skip on agg steps: A_lo == 0)
                if (cur_feat)
                    mma_f16(d, qa[mt][0].z, qa[mt][1].z, qa[mt][0].w, qa[mt][1].w,
                            qb.x, qb.y);
            }
        }
    }

    // ---- epilogue: + bias, guarded float2 stores ----
#pragma unroll
    for (int mt = 0; mt < 2; mt++) {
        int row0 = m0 + wm * 32 + mt * 16 + lq;
#pragma unroll
        for (int nt = 0; nt < 8; nt++) {
            int col = wn * 64 + nt * 8 + 2 * lk;
            float b0 = bias[col];
            float b1 = bias[col + 1];
            float* d = acc[mt][nt];
            if (row0 < NN)
                *reinterpret_cast<float2*>(out + (size_t)row0 * F + col) =
                    make_float2(d[0] + b0, d[1] + b1);
            if (row0 + 8 < NN)
                *reinterpret_cast<float2*>(out + (size_t)(row0 + 8) * F + col) =
                    make_float2(d[2] + b0, d[3] + b1);
        }
    }
}

// ---------------------------------------------------------------------------
// Launch
// ---------------------------------------------------------------------------
extern "C" void kernel_launch(void* const* d_in, const int* in_sizes, int n_in,
                              void* d_out, int out_size) {
    const float* feat = nullptr;
    const float* tv   = nullptr;
    const int*   ti   = nullptr;
    const int*   src  = nullptr;
    const int*   dst  = nullptr;
    const float* Ws   = nullptr;
    const float* Wn   = nullptr;
    const float* bs   = nullptr;

    for (int i = 0; i < n_in; i++) {
        int sz = in_sizes[i];
        if (sz == NN * F) {
            feat = (const float*)d_in[i];
        } else if (sz == NN * KT) {
            if (!tv) tv = (const float*)d_in[i];
            else     ti = (const int*)d_in[i];
        } else if (sz == EE) {
            if (!src) src = (const int*)d_in[i];
            else      dst = (const int*)d_in[i];
        } else if (sz == F * F) {
            if (!Ws) Ws = (const float*)d_in[i];
            else     Wn = (const float*)d_in[i];
        } else if (sz == F) {
            bs = (const float*)d_in[i];
        }
    }
    float* out = (float*)d_out;

    k_expand<<<(NN + 7) / 8, 256>>>(tv, ti);
    k_prepb<<<16, 512>>>(Ws, Wn);
    k_fill<<<(EE + 255) / 256, 256>>>(src, dst);
    k_gather<<<(NN + 7) / 8, 256>>>();
    k_gemm<<<(NN + 127) / 128, 256>>>(feat, bs, out);
}

// round 14
// speedup vs baseline: 1.9132x; 1.0827x over previous
#include <cuda_runtime.h>
#include <cuda_fp16.h>
#include <cstdint>

#define NN 50000
#define EE 800000
#define F  128
#define KT 32
#define CAP 96

#define EXP_BLOCKS  6250   // expand: 8 nodes/block
#define FILL_BLOCKS 3125   // fill:   256 edges/block
#define PB_BLOCKS   32     // prepb:  half a k16-step/block

// Scratch (static __device__ — no allocation anywhere).
// INVARIANT: g_cnt is all-zero at kernel_launch entry (zero-init at load;
// k_gather re-zeroes each counter after consuming it -> holds on every replay).
__device__ int    g_cnt[NN];
__device__ int    g_csr[(size_t)NN * CAP];
__device__ __half g_xsh[(size_t)NN * F];      // dense fp16 x_sparse rows
__device__ __half g_aggh[(size_t)NN * F];     // fp16 agg
__device__ uint4  g_bs16[16 * 512];           // B split fp16, fragment-native

// ---------------------------------------------------------------------------
__device__ __forceinline__ unsigned pack2(float x, float y) {
    __half2 h = __floats2half2_rn(x, y);
    return *reinterpret_cast<unsigned*>(&h);
}
__device__ __forceinline__ void split16(float x, float& h, float& l) {
    __half hh = __float2half_rn(x);
    h = __half2float(hh);
    l = x - h;
}
__device__ __forceinline__ void mma_f16(float* d,
                                        unsigned a0, unsigned a1,
                                        unsigned a2, unsigned a3,
                                        unsigned b0, unsigned b1) {
    asm volatile(
        "mma.sync.aligned.m16n8k16.row.col.f32.f16.f16.f32 "
        "{%0,%1,%2,%3}, {%4,%5,%6,%7}, {%8,%9}, {%0,%1,%2,%3};"
        : "+f"(d[0]), "+f"(d[1]), "+f"(d[2]), "+f"(d[3])
        : "r"(a0), "r"(a1), "r"(a2), "r"(a3), "r"(b0), "r"(b1));
}

// ---------------------------------------------------------------------------
// K1: fused front end — three independent jobs dispatched by block range.
//   [0, 6250)        expand top-k into dense fp16 rows (last-wins dedup)
//   [6250, 9375)     fill padded CSR (g_cnt pre-zeroed by invariant)
//   [9375, 9407)     split B into fragment-native fp16 hi/lo layout
// ---------------------------------------------------------------------------
__global__ __launch_bounds__(256) void k_front(
        const float* __restrict__ topk_values,
        const int*  __restrict__ topk_indices,
        const int*  __restrict__ src,
        const int*  __restrict__ dst,
        const float* __restrict__ Wself,
        const float* __restrict__ Wneigh) {
    const int bid = blockIdx.x;
    const int tid = threadIdx.x;

    if (bid < EXP_BLOCKS) {
        // ---- expand ----
        __shared__ __half srow[8][F];
        int wib  = tid >> 5;
        int lane = tid & 31;
        int w = bid * 8 + wib;
        if (w >= NN) return;

        *reinterpret_cast<uint2*>(&srow[wib][lane * 4]) = make_uint2(0u, 0u);
        __syncwarp();

        float v  = topk_values[(size_t)w * KT + lane];
        int  idx = topk_indices[(size_t)w * KT + lane];
        unsigned m = __match_any_sync(0xffffffffu, idx);
        int leader = 31 - __clz(m);      // highest lane with this index wins
        if (lane == leader)
            srow[wib][idx & 127] = __float2half(v);
        __syncwarp();

        *reinterpret_cast<uint2*>(g_xsh + (size_t)w * F + lane * 4) =
            *reinterpret_cast<uint2*>(&srow[wib][lane * 4]);
    } else if (bid < EXP_BLOCKS + FILL_BLOCKS) {
        // ---- fill ----
        int e = (bid - EXP_BLOCKS) * 256 + tid;
        if (e >= EE) return;
        int d = dst[e];
        int slot = atomicAdd(&g_cnt[d], 1);
        if (slot < CAP) g_csr[(size_t)d * CAP + slot] = src[e];
    } else {
        // ---- prepb ----
        int pb = bid - (EXP_BLOCKS + FILL_BLOCKS);   // 0..31
        int ks = pb >> 1;                            // 0..15
        int tt = (pb & 1) * 256 + tid;               // 0..511
        int n  = tt >> 2;
        int j  = tt & 3;
        const float* W = (ks < 8) ? Wself : Wneigh;
        int kl = (ks & 7) * 16;
        float w0 = W[(size_t)(kl + 2 * j)     * F + n];
        float w1 = W[(size_t)(kl + 2 * j + 1) * F + n];
        float w2 = W[(size_t)(kl + 2 * j + 8) * F + n];
        float w3 = W[(size_t)(kl + 2 * j + 9) * F + n];
        float h0, l0, h1, l1, h2, l2, h3, l3;
        split16(w0, h0, l0); split16(w1, h1, l1);
        split16(w2, h2, l2); split16(w3, h3, l3);
        uint4 v;
        v.x = pack2(h0, h1);
        v.y = pack2(h2, h3);
        v.z = pack2(l0, l1);
        v.w = pack2(l2, l3);
        g_bs16[ks * 512 + n * 4 + j] = v;
    }
}

// ---------------------------------------------------------------------------
// K2: gather SpMM — warp per dst, register accumulation, 4-edge batching
//     (4 independent LDG.64 in flight on the shfl->load critical chain).
//     Re-zeroes g_cnt[n] after use to restore the launch invariant.
// ---------------------------------------------------------------------------
__global__ __launch_bounds__(256) void k_gather() {
    int wib  = threadIdx.x >> 5;
    int lane = threadIdx.x & 31;
    int n = blockIdx.x * 8 + wib;
    if (n >= NN) return;

    float a0 = 0.f, a1 = 0.f, a2 = 0.f, a3 = 0.f;

    int cnt = g_cnt[n];
    int deg = cnt < CAP ? cnt : CAP;

    for (int base = 0; base < deg; base += 32) {
        int eid = base + lane;
        int sl = (eid < deg) ? __ldg(&g_csr[(size_t)n * CAP + eid]) : 0;
        int lim = deg - base; if (lim > 32) lim = 32;
        int j = 0;
        for (; j + 4 <= lim; j += 4) {
            int s0 = __shfl_sync(0xffffffffu, sl, j);
            int s1 = __shfl_sync(0xffffffffu, sl, j + 1);
            int s2 = __shfl_sync(0xffffffffu, sl, j + 2);
            int s3 = __shfl_sync(0xffffffffu, sl, j + 3);
            uint2 u0 = *reinterpret_cast<const uint2*>(g_xsh + (size_t)s0 * F + lane * 4);
            uint2 u1 = *reinterpret_cast<const uint2*>(g_xsh + (size_t)s1 * F + lane * 4);
            uint2 u2 = *reinterpret_cast<const uint2*>(g_xsh + (size_t)s2 * F + lane * 4);
            uint2 u3 = *reinterpret_cast<const uint2*>(g_xsh + (size_t)s3 * F + lane * 4);
            float2 f;
            f = __half22float2(*reinterpret_cast<__half2*>(&u0.x)); a0 += f.x; a1 += f.y;
            f = __half22float2(*reinterpret_cast<__half2*>(&u0.y)); a2 += f.x; a3 += f.y;
            f = __half22float2(*reinterpret_cast<__half2*>(&u1.x)); a0 += f.x; a1 += f.y;
            f = __half22float2(*reinterpret_cast<__half2*>(&u1.y)); a2 += f.x; a3 += f.y;
            f = __half22float2(*reinterpret_cast<__half2*>(&u2.x)); a0 += f.x; a1 += f.y;
            f = __half22float2(*reinterpret_cast<__half2*>(&u2.y)); a2 += f.x; a3 += f.y;
            f = __half22float2(*reinterpret_cast<__half2*>(&u3.x)); a0 += f.x; a1 += f.y;
            f = __half22float2(*reinterpret_cast<__half2*>(&u3.y)); a2 += f.x; a3 += f.y;
        }
        for (; j < lim; j++) {
            int s = __shfl_sync(0xffffffffu, sl, j);
            uint2 u = *reinterpret_cast<const uint2*>(g_xsh + (size_t)s * F + lane * 4);
            float2 f0 = __half22float2(*reinterpret_cast<__half2*>(&u.x));
            float2 f1 = __half22float2(*reinterpret_cast<__half2*>(&u.y));
            a0 += f0.x; a1 += f0.y; a2 += f1.x; a3 += f1.y;
        }
    }

    float winv = 1.0f / (float)(cnt > 0 ? cnt : 1);
    __half2 h01 = __floats2half2_rn(a0 * winv, a1 * winv);
    __half2 h23 = __floats2half2_rn(a2 * winv, a3 * winv);
    uint2 st;
    st.x = *reinterpret_cast<unsigned*>(&h01);
    st.y = *reinterpret_cast<unsigned*>(&h23);
    *reinterpret_cast<uint2*>(g_aggh + (size_t)n * F + lane * 4) = st;

    if (lane == 0) g_cnt[n] = 0;     // restore invariant for next replay
}

// ---------------------------------------------------------------------------
// K3: out = [feat|agg] @ [Wself;Wneigh] + b via split-FP16 HMMA m16n8k16.
// BM=128, BN=128, BK=16, 16 k-steps, double buffer, 1 barrier/step.
// feat steps: 3 HMMA/tile; agg steps: 2 (A exactly fp16 -> A_lo == 0).
// ---------------------------------------------------------------------------
__global__ __launch_bounds__(256, 2) void k_gemm(const float* __restrict__ feat,
                                                 const float* __restrict__ bias,
                                                 float* __restrict__ out) {
    __shared__ uint4 As[2][128][4];   // 8 KB per buf
    __shared__ uint4 Bs[2][128][4];

    const int m0   = blockIdx.x * 128;
    const int t    = threadIdx.x;
    const int lane = t & 31;
    const int wid  = t >> 5;
    const int wm   = wid >> 1;        // 0..3 -> m offset wm*32
    const int wn   = wid & 1;         // 0..1 -> n offset wn*64
    const int lk   = lane & 3;
    const int lq   = lane >> 2;

    // A loader: 4 threads per row, 2 row-passes (ar, ar+64); slot aj.
    const int ar = t >> 2;            // 0..63
    const int aj = t & 3;
    int gr0 = m0 + ar;      if (gr0 > NN - 1) gr0 = NN - 1;
    int gr1 = m0 + ar + 64; if (gr1 > NN - 1) gr1 = NN - 1;

    // B copy: uint4s t and t+256 of the 512-uint4 step block
    const int bn0 = t >> 2;
    const int bc0 = t & 3;

    float acc[2][8][4];
#pragma unroll
    for (int mt = 0; mt < 2; mt++)
#pragma unroll
        for (int nt = 0; nt < 8; nt++)
#pragma unroll
            for (int r = 0; r < 4; r++) acc[mt][nt][r] = 0.0f;

    // Staging regs
    float2 fa[2][2];   // feat: [pass][k-half]
    uint2  ua[2];      // agg:  [pass]
    uint4  bq0, bq1;

    // Prologue: stage k-step 0 (feat)
    {
        const float* p0 = feat + (size_t)gr0 * F + 2 * aj;
        const float* p1 = feat + (size_t)gr1 * F + 2 * aj;
        fa[0][0] = *reinterpret_cast<const float2*>(p0);
        fa[0][1] = *reinterpret_cast<const float2*>(p0 + 8);
        fa[1][0] = *reinterpret_cast<const float2*>(p1);
        fa[1][1] = *reinterpret_cast<const float2*>(p1 + 8);
        bq0 = g_bs16[t];
        bq1 = g_bs16[256 + t];
    }

#pragma unroll 1
    for (int kb = 0; kb < 16; kb++) {
        const int buf = kb & 1;
        const bool cur_feat = (kb < 8);

        // ---- store staged regs -> smem (split A here) ----
        if (cur_feat) {
#pragma unroll
            for (int p = 0; p < 2; p++) {
                float h0, l0, h1, l1, h2, l2, h3, l3;
                split16(fa[p][0].x, h0, l0); split16(fa[p][0].y, h1, l1);
                split16(fa[p][1].x, h2, l2); split16(fa[p][1].y, h3, l3);
                uint4 v;
                v.x = pack2(h0, h1);
                v.y = pack2(h2, h3);
                v.z = pack2(l0, l1);
                v.w = pack2(l2, l3);
                As[buf][ar + p * 64][aj] = v;
            }
        } else {
#pragma unroll
            for (int p = 0; p < 2; p++) {
                uint4 v;
                v.x = ua[p].x; v.y = ua[p].y; v.z = 0u; v.w = 0u;
                As[buf][ar + p * 64][aj] = v;
            }
        }
        Bs[buf][bn0][bc0]      = bq0;
        Bs[buf][bn0 + 64][bc0] = bq1;
        __syncthreads();

        // ---- prefetch next k-step ----
        if (kb < 15) {
            const int kn = kb + 1;
            if (kn < 8) {
                const float* p0 = feat + (size_t)gr0 * F + kn * 16 + 2 * aj;
                const float* p1 = feat + (size_t)gr1 * F + kn * 16 + 2 * aj;
                fa[0][0] = *reinterpret_cast<const float2*>(p0);
                fa[0][1] = *reinterpret_cast<const float2*>(p0 + 8);
                fa[1][0] = *reinterpret_cast<const float2*>(p1);
                fa[1][1] = *reinterpret_cast<const float2*>(p1 + 8);
            } else {
                const __half* q0 = g_aggh + (size_t)gr0 * F + (kn - 8) * 16 + 2 * aj;
                const __half* q1 = g_aggh + (size_t)gr1 * F + (kn - 8) * 16 + 2 * aj;
                ua[0].x = *reinterpret_cast<const unsigned*>(q0);
                ua[0].y = *reinterpret_cast<const unsigned*>(q0 + 8);
                ua[1].x = *reinterpret_cast<const unsigned*>(q1);
                ua[1].y = *reinterpret_cast<const unsigned*>(q1 + 8);
            }
            bq0 = g_bs16[kn * 512 + t];
            bq1 = g_bs16[kn * 512 + 256 + t];
        }

        // ---- compute current buffer ----
        uint4 qa[2][2];
#pragma unroll
        for (int mt = 0; mt < 2; mt++) {
            int r0 = wm * 32 + mt * 16 + lq;
            qa[mt][0] = As[buf][r0][lk];
            qa[mt][1] = As[buf][r0 + 8][lk];
        }
#pragma unroll
        for (int nt = 0; nt < 8; nt++) {
            uint4 qb = Bs[buf][wn * 64 + nt * 8 + lq][lk];
#pragma unroll
            for (int mt = 0; mt < 2; mt++) {
                float* d = acc[mt][nt];
                // Ahi * Bhi
                mma_f16(d, qa[mt][0].x, qa[mt][1].x, qa[mt][0].y, qa[mt][1].y,
                        qb.x, qb.y);
                // Ahi * Blo
                mma_f16(d, qa[mt][0].x, qa[mt][1].x, qa[mt][0].y, qa[mt][1].y,
                        qb.z, qb.w);
                // Alo * Bhi (skip on agg steps: A_lo == 0)
                if (cur_feat)
                    mma_f16(d, qa[mt][0].z, qa[mt][1].z, qa[mt][0].w, qa[mt][1].w,
                            qb.x, qb.y);
            }
        }
    }

    // ---- epilogue: + bias, guarded float2 stores ----
#pragma unroll
    for (int mt = 0; mt < 2; mt++) {
        int row0 = m0 + wm * 32 + mt * 16 + lq;
#pragma unroll
        for (int nt = 0; nt < 8; nt++) {
            int col = wn * 64 + nt * 8 + 2 * lk;
            float b0 = bias[col];
            float b1 = bias[col + 1];
            float* d = acc[mt][nt];
            if (row0 < NN)
                *reinterpret_cast<float2*>(out + (size_t)row0 * F + col) =
                    make_float2(d[0] + b0, d[1] + b1);
            if (row0 + 8 < NN)
                *reinterpret_cast<float2*>(out + (size_t)(row0 + 8) * F + col) =
                    make_float2(d[2] + b0, d[3] + b1);
        }
    }
}

// ---------------------------------------------------------------------------
// Launch
// ---------------------------------------------------------------------------
extern "C" void kernel_launch(void* const* d_in, const int* in_sizes, int n_in,
                              void* d_out, int out_size) {
    const float* feat = nullptr;
    const float* tv   = nullptr;
    const int*   ti   = nullptr;
    const int*   src  = nullptr;
    const int*   dst  = nullptr;
    const float* Ws   = nullptr;
    const float* Wn   = nullptr;
    const float* bs   = nullptr;

    for (int i = 0; i < n_in; i++) {
        int sz = in_sizes[i];
        if (sz == NN * F) {
            feat = (const float*)d_in[i];
        } else if (sz == NN * KT) {
            if (!tv) tv = (const float*)d_in[i];
            else     ti = (const int*)d_in[i];
        } else if (sz == EE) {
            if (!src) src = (const int*)d_in[i];
            else      dst = (const int*)d_in[i];
        } else if (sz == F * F) {
            if (!Ws) Ws = (const float*)d_in[i];
            else     Wn = (const float*)d_in[i];
        } else if (sz == F) {
            bs = (const float*)d_in[i];
        }
    }
    float* out = (float*)d_out;

    k_front<<<EXP_BLOCKS + FILL_BLOCKS + PB_BLOCKS, 256>>>(tv, ti, src, dst, Ws, Wn);
    k_gather<<<(NN + 7) / 8, 256>>>();
    k_gemm<<<(NN + 127) / 128, 256>>>(feat, bs, out);
}

// round 17
// speedup vs baseline: 2.3595x; 1.2333x over previous
#include <cuda_runtime.h>
#include <cuda_fp16.h>
#include <cstdint>

#define NN 50000
#define EE 800000
#define F  128
#define KT 32
#define CAP 96

#define EXP_BLOCKS  1563   // expand: 8 warps x 4 nodes = 32 nodes/block
#define FILL_BLOCKS 782    // fill:   1024 edges/block (4 per thread)
#define PB_BLOCKS   32     // prepb:  half a k16-step/block

// Scratch (static __device__ — no allocation anywhere).
// INVARIANT: g_cnt is all-zero at kernel_launch entry (zero-init at load;
// k_gather re-zeroes each counter after consuming it -> holds on every replay).
__device__ int    g_cnt[NN];
__device__ int    g_csr[(size_t)NN * CAP];
__device__ __half g_xsh[(size_t)NN * F];      // dense fp16 x_sparse rows
__device__ __half g_aggh[(size_t)NN * F];     // fp16 agg
__device__ uint2  g_bsw[16 * 512];            // B fp16 fragment-native, swizzled

// ---------------------------------------------------------------------------
__device__ __forceinline__ unsigned pack2(float x, float y) {
    __half2 h = __floats2half2_rn(x, y);
    return *reinterpret_cast<unsigned*>(&h);
}
__device__ __forceinline__ void mma_f16(float* d,
                                        unsigned a0, unsigned a1,
                                        unsigned a2, unsigned a3,
                                        unsigned b0, unsigned b1) {
    asm volatile(
        "mma.sync.aligned.m16n8k16.row.col.f32.f16.f16.f32 "
        "{%0,%1,%2,%3}, {%4,%5,%6,%7}, {%8,%9}, {%0,%1,%2,%3};"
        : "+f"(d[0]), "+f"(d[1]), "+f"(d[2]), "+f"(d[3])
        : "r"(a0), "r"(a1), "r"(a2), "r"(a3), "r"(b0), "r"(b1));
}

// ---------------------------------------------------------------------------
// K1: fused front end — three independent jobs dispatched by block range.
//   [0, 1563)       expand: 4 nodes/warp, MLP-4 on the load chain
//   [1563, 2345)    fill CSR: 4 edges/thread, batched loads + atomics
//   [2345, 2377)    split B into fp16 fragment-native swizzled layout
// ---------------------------------------------------------------------------
__global__ __launch_bounds__(256) void k_front(
        const float* __restrict__ topk_values,
        const int*  __restrict__ topk_indices,
        const int*  __restrict__ src,
        const int*  __restrict__ dst,
        const float* __restrict__ Wself,
        const float* __restrict__ Wneigh) {
    const int bid = blockIdx.x;
    const int tid = threadIdx.x;

    if (bid < EXP_BLOCKS) {
        // ---- expand: warp handles nodes w0..w0+3 ----
        __shared__ __half srow[32][F];    // 8 KB
        int wib  = tid >> 5;
        int lane = tid & 31;
        int w0 = (bid * 8 + wib) * 4;

        float v[4]; int idx[4];
#pragma unroll
        for (int r = 0; r < 4; r++) {
            int w = w0 + r;
            if (w < NN) {
                v[r]   = topk_values[(size_t)w * KT + lane];
                idx[r] = topk_indices[(size_t)w * KT + lane];
            } else { v[r] = 0.f; idx[r] = 0; }
        }
#pragma unroll
        for (int r = 0; r < 4; r++)
            *reinterpret_cast<uint2*>(&srow[wib * 4 + r][lane * 4]) =
                make_uint2(0u, 0u);
        __syncwarp();
#pragma unroll
        for (int r = 0; r < 4; r++) {
            unsigned m = __match_any_sync(0xffffffffu, idx[r]);
            int leader = 31 - __clz(m);   // highest lane wins (last-wins)
            if (lane == leader)
                srow[wib * 4 + r][idx[r] & 127] = __float2half(v[r]);
        }
        __syncwarp();
#pragma unroll
        for (int r = 0; r < 4; r++) {
            int w = w0 + r;
            if (w < NN)
                *reinterpret_cast<uint2*>(g_xsh + (size_t)w * F + lane * 4) =
                    *reinterpret_cast<uint2*>(&srow[wib * 4 + r][lane * 4]);
        }
    } else if (bid < EXP_BLOCKS + FILL_BLOCKS) {
        // ---- fill: 4 edges per thread ----
        int base = (bid - EXP_BLOCKS) * 1024 + tid;
        int dd[4], ss[4];
#pragma unroll
        for (int r = 0; r < 4; r++) {
            int e = base + r * 256;
            if (e < EE) { dd[r] = dst[e]; ss[r] = src[e]; }
            else        { dd[r] = -1; ss[r] = 0; }
        }
#pragma unroll
        for (int r = 0; r < 4; r++) {
            if (dd[r] >= 0) {
                int slot = atomicAdd(&g_cnt[dd[r]], 1);
                if (slot < CAP) g_csr[(size_t)dd[r] * CAP + slot] = ss[r];
            }
        }
    } else {
        // ---- prepb: fp16 B, fragment-native, swizzled ----
        int pb = bid - (EXP_BLOCKS + FILL_BLOCKS);   // 0..31
        int ks = pb >> 1;                            // 0..15
        int tt = (pb & 1) * 256 + tid;               // 0..511
        int n  = tt >> 2;
        int j  = tt & 3;
        const float* W = (ks < 8) ? Wself : Wneigh;
        int kl = (ks & 7) * 16;
        float w0 = W[(size_t)(kl + 2 * j)     * F + n];
        float w1 = W[(size_t)(kl + 2 * j + 1) * F + n];
        float w2 = W[(size_t)(kl + 2 * j + 8) * F + n];
        float w3 = W[(size_t)(kl + 2 * j + 9) * F + n];
        uint2 v;
        v.x = pack2(w0, w1);
        v.y = pack2(w2, w3);
        g_bsw[ks * 512 + n * 4 + (j ^ (n & 3))] = v;
    }
}

// ---------------------------------------------------------------------------
// K2: gather SpMM — warp per dst, register accumulation, 4-edge batching.
//     Re-zeroes g_cnt[n] after use to restore the launch invariant.
// ---------------------------------------------------------------------------
__global__ __launch_bounds__(256) void k_gather() {
    int wib  = threadIdx.x >> 5;
    int lane = threadIdx.x & 31;
    int n = blockIdx.x * 8 + wib;
    if (n >= NN) return;

    float a0 = 0.f, a1 = 0.f, a2 = 0.f, a3 = 0.f;

    int cnt = g_cnt[n];
    int deg = cnt < CAP ? cnt : CAP;

    for (int base = 0; base < deg; base += 32) {
        int eid = base + lane;
        int sl = (eid < deg) ? __ldg(&g_csr[(size_t)n * CAP + eid]) : 0;
        int lim = deg - base; if (lim > 32) lim = 32;
        int j = 0;
        for (; j + 4 <= lim; j += 4) {
            int s0 = __shfl_sync(0xffffffffu, sl, j);
            int s1 = __shfl_sync(0xffffffffu, sl, j + 1);
            int s2 = __shfl_sync(0xffffffffu, sl, j + 2);
            int s3 = __shfl_sync(0xffffffffu, sl, j + 3);
            uint2 u0 = *reinterpret_cast<const uint2*>(g_xsh + (size_t)s0 * F + lane * 4);
            uint2 u1 = *reinterpret_cast<const uint2*>(g_xsh + (size_t)s1 * F + lane * 4);
            uint2 u2 = *reinterpret_cast<const uint2*>(g_xsh + (size_t)s2 * F + lane * 4);
            uint2 u3 = *reinterpret_cast<const uint2*>(g_xsh + (size_t)s3 * F + lane * 4);
            float2 f;
            f = __half22float2(*reinterpret_cast<__half2*>(&u0.x)); a0 += f.x; a1 += f.y;
            f = __half22float2(*reinterpret_cast<__half2*>(&u0.y)); a2 += f.x; a3 += f.y;
            f = __half22float2(*reinterpret_cast<__half2*>(&u1.x)); a0 += f.x; a1 += f.y;
            f = __half22float2(*reinterpret_cast<__half2*>(&u1.y)); a2 += f.x; a3 += f.y;
            f = __half22float2(*reinterpret_cast<__half2*>(&u2.x)); a0 += f.x; a1 += f.y;
            f = __half22float2(*reinterpret_cast<__half2*>(&u2.y)); a2 += f.x; a3 += f.y;
            f = __half22float2(*reinterpret_cast<__half2*>(&u3.x)); a0 += f.x; a1 += f.y;
            f = __half22float2(*reinterpret_cast<__half2*>(&u3.y)); a2 += f.x; a3 += f.y;
        }
        for (; j < lim; j++) {
            int s = __shfl_sync(0xffffffffu, sl, j);
            uint2 u = *reinterpret_cast<const uint2*>(g_xsh + (size_t)s * F + lane * 4);
            float2 f0 = __half22float2(*reinterpret_cast<__half2*>(&u.x));
            float2 f1 = __half22float2(*reinterpret_cast<__half2*>(&u.y));
            a0 += f0.x; a1 += f0.y; a2 += f1.x; a3 += f1.y;
        }
    }

    float winv = 1.0f / (float)(cnt > 0 ? cnt : 1);
    __half2 h01 = __floats2half2_rn(a0 * winv, a1 * winv);
    __half2 h23 = __floats2half2_rn(a2 * winv, a3 * winv);
    uint2 st;
    st.x = *reinterpret_cast<unsigned*>(&h01);
    st.y = *reinterpret_cast<unsigned*>(&h23);
    *reinterpret_cast<uint2*>(g_aggh + (size_t)n * F + lane * 4) = st;

    if (lane == 0) g_cnt[n] = 0;     // restore invariant for next replay
}

// ---------------------------------------------------------------------------
// K3: out = [feat|agg] @ [Wself;Wneigh] + b — pure fp16 HMMA m16n8k16.
// BM=128, BN=128, BK=16, 16 k-steps, double buffer, 1 barrier/step.
// smem: [row][slot] uint2 = (half2(k=2j,2j+1), half2(k=2j+8,2j+9)),
// slot physically at j ^ (row&3) -> LDS.64/STS.64 conflict-free.
// ONE HMMA per (16x8) tile per k-step.
// ---------------------------------------------------------------------------
__global__ __launch_bounds__(256, 2) void k_gemm(const float* __restrict__ feat,
                                                 const float* __restrict__ bias,
                                                 float* __restrict__ out) {
    __shared__ uint2 As[2][128][4];   // 4 KB per buf
    __shared__ uint2 Bs[2][128][4];

    const int m0   = blockIdx.x * 128;
    const int t    = threadIdx.x;
    const int lane = t & 31;
    const int wid  = t >> 5;
    const int wm   = wid >> 1;        // 0..3 -> m offset wm*32
    const int wn   = wid & 1;         // 0..1 -> n offset wn*64
    const int lk   = lane & 3;
    const int lq   = lane >> 2;

    // A loader: 4 threads per row, 2 row-passes (ar, ar+64); logical slot aj.
    const int ar = t >> 2;            // 0..63
    const int aj = t & 3;
    int gr0 = m0 + ar;      if (gr0 > NN - 1) gr0 = NN - 1;
    int gr1 = m0 + ar + 64; if (gr1 > NN - 1) gr1 = NN - 1;

    float acc[2][8][4];
#pragma unroll
    for (int mt = 0; mt < 2; mt++)
#pragma unroll
        for (int nt = 0; nt < 8; nt++)
#pragma unroll
            for (int r = 0; r < 4; r++) acc[mt][nt][r] = 0.0f;

    // Staging regs
    float2 fa[2][2];   // feat: [pass][k-half] = cols (2aj,2aj+1), (2aj+8,2aj+9)
    uint2  ua[2];      // agg:  [pass]
    uint2  bq0, bq1;

    // Prologue: stage k-step 0 (feat)
    {
        const float* p0 = feat + (size_t)gr0 * F + 2 * aj;
        const float* p1 = feat + (size_t)gr1 * F + 2 * aj;
        fa[0][0] = *reinterpret_cast<const float2*>(p0);
        fa[0][1] = *reinterpret_cast<const float2*>(p0 + 8);
        fa[1][0] = *reinterpret_cast<const float2*>(p1);
        fa[1][1] = *reinterpret_cast<const float2*>(p1 + 8);
        bq0 = g_bsw[t];
        bq1 = g_bsw[256 + t];
    }

#pragma unroll 1
    for (int kb = 0; kb < 16; kb++) {
        const int buf = kb & 1;
        const bool cur_feat = (kb < 8);

        // ---- store staged regs -> smem (fp16 convert here) ----
#pragma unroll
        for (int p = 0; p < 2; p++) {
            int row = ar + p * 64;
            uint2 v;
            if (cur_feat) {
                v.x = pack2(fa[p][0].x, fa[p][0].y);
                v.y = pack2(fa[p][1].x, fa[p][1].y);
            } else {
                v = ua[p];
            }
            As[buf][row][aj ^ (row & 3)] = v;
        }
        // B copy: entries t and t+256 of the 512-uint2 step block (pre-swizzled)
        {
            int n0 = t >> 2, c0 = t & 3;
            Bs[buf][n0][c0]      = bq0;
            Bs[buf][n0 + 64][c0] = bq1;
        }
        __syncthreads();

        // ---- prefetch next k-step ----
        if (kb < 15) {
            const int kn = kb + 1;
            if (kn < 8) {
                const float* p0 = feat + (size_t)gr0 * F + kn * 16 + 2 * aj;
                const float* p1 = feat + (size_t)gr1 * F + kn * 16 + 2 * aj;
                fa[0][0] = *reinterpret_cast<const float2*>(p0);
                fa[0][1] = *reinterpret_cast<const float2*>(p0 + 8);
                fa[1][0] = *reinterpret_cast<const float2*>(p1);
                fa[1][1] = *reinterpret_cast<const float2*>(p1 + 8);
            } else {
                const __half* q0 = g_aggh + (size_t)gr0 * F + (kn - 8) * 16 + 2 * aj;
                const __half* q1 = g_aggh + (size_t)gr1 * F + (kn - 8) * 16 + 2 * aj;
                ua[0].x = *reinterpret_cast<const unsigned*>(q0);
                ua[0].y = *reinterpret_cast<const unsigned*>(q0 + 8);
                ua[1].x = *reinterpret_cast<const unsigned*>(q1);
                ua[1].y = *reinterpret_cast<const unsigned*>(q1 + 8);
            }
            bq0 = g_bsw[kn * 512 + t];
            bq1 = g_bsw[kn * 512 + 256 + t];
        }

        // ---- compute current buffer: 16 HMMA per warp per step ----
        uint2 qa0[2], qa1[2];
#pragma unroll
        for (int mt = 0; mt < 2; mt++) {
            int r0 = wm * 32 + mt * 16 + lq;
            qa0[mt] = As[buf][r0][lk ^ (r0 & 3)];          // (a0, a2)
            qa1[mt] = As[buf][r0 + 8][lk ^ (r0 & 3)];      // (a1, a3)
        }
#pragma unroll
        for (int nt = 0; nt < 8; nt++) {
            int n = wn * 64 + nt * 8 + lq;
            uint2 qb = Bs[buf][n][lk ^ (n & 3)];           // (b0, b1)
#pragma unroll
            for (int mt = 0; mt < 2; mt++)
                mma_f16(acc[mt][nt],
                        qa0[mt].x, qa1[mt].x, qa0[mt].y, qa1[mt].y,
                        qb.x, qb.y);
        }
    }

    // ---- epilogue: + bias, guarded float2 stores ----
#pragma unroll
    for (int mt = 0; mt < 2; mt++) {
        int row0 = m0 + wm * 32 + mt * 16 + lq;
#pragma unroll
        for (int nt = 0; nt < 8; nt++) {
            int col = wn * 64 + nt * 8 + 2 * lk;
            float b0 = bias[col];
            float b1 = bias[col + 1];
            float* d = acc[mt][nt];
            if (row0 < NN)
                *reinterpret_cast<float2*>(out + (size_t)row0 * F + col) =
                    make_float2(d[0] + b0, d[1] + b1);
            if (row0 + 8 < NN)
                *reinterpret_cast<float2*>(out + (size_t)(row0 + 8) * F + col) =
                    make_float2(d[2] + b0, d[3] + b1);
        }
    }
}

// ---------------------------------------------------------------------------
// Launch
// ---------------------------------------------------------------------------
extern "C" void kernel_launch(void* const* d_in, const int* in_sizes, int n_in,
                              void* d_out, int out_size) {
    const float* feat = nullptr;
    const float* tv   = nullptr;
    const int*   ti   = nullptr;
    const int*   src  = nullptr;
    const int*   dst  = nullptr;
    const float* Ws   = nullptr;
    const float* Wn   = nullptr;
    const float* bs   = nullptr;

    for (int i = 0; i < n_in; i++) {
        int sz = in_sizes[i];
        if (sz == NN * F) {
            feat = (const float*)d_in[i];
        } else if (sz == NN * KT) {
            if (!tv) tv = (const float*)d_in[i];
            else     ti = (const int*)d_in[i];
        } else if (sz == EE) {
            if (!src) src = (const int*)d_in[i];
            else      dst = (const int*)d_in[i];
        } else if (sz == F * F) {
            if (!Ws) Ws = (const float*)d_in[i];
            else     Wn = (const float*)d_in[i];
        } else if (sz == F) {
            bs = (const float*)d_in[i];
        }
    }
    float* out = (float*)d_out;

    k_front<<<EXP_BLOCKS + FILL_BLOCKS + PB_BLOCKS, 256>>>(tv, ti, src, dst, Ws, Wn);
    k_gather<<<(NN + 7) / 8, 256>>>();
    k_gemm<<<(NN + 127) / 128, 256>>>(feat, bs, out);
}